// round 2
// baseline (speedup 1.0000x reference)
#include <cuda_runtime.h>

// dense_image_warp: out[b,y,x,c] = bilinear(image[b], y - flow[b,y,x,0], x - flow[b,y,x,1])
// B=8, H=512, W=512, C=16, fp32. Shapes hardcoded per setup_inputs.
// Two output float4 elements per thread (offset by half) for doubled MLP.

#define Hh 512
#define Ww 512

__global__ __launch_bounds__(256) void warp_kernel2(
    const float4* __restrict__ img4,   // image as float4 (4 channels per group)
    const float2* __restrict__ flow2,  // flow as float2 per pixel
    float4* __restrict__ out4,
    int half)                          // n_float4 / 2
{
    int t = blockIdx.x * blockDim.x + threadIdx.x;
    if (t >= half) return;

    int t0 = t;
    int t1 = t + half;

    int p0 = t0 >> 2, cg0 = t0 & 3;
    int p1 = t1 >> 2, cg1 = t1 & 3;

    // Issue both flow loads first (independent)
    float2 f0 = __ldg(&flow2[p0]);
    float2 f1 = __ldg(&flow2[p1]);

    // ---- element 0 address math ----
    int x0 = p0 & (Ww - 1);
    int y0 = (p0 >> 9) & (Hh - 1);
    int b0 = p0 >> 18;
    float qy0 = (float)y0 - f0.x;
    float qx0 = (float)x0 - f0.y;
    float fy0 = fminf(fmaxf(floorf(qy0), 0.0f), (float)(Hh - 2));
    float fx0 = fminf(fmaxf(floorf(qx0), 0.0f), (float)(Ww - 2));
    float ay0 = fminf(fmaxf(qy0 - fy0, 0.0f), 1.0f);
    float ax0 = fminf(fmaxf(qx0 - fx0, 0.0f), 1.0f);
    int iy0 = (int)fy0, ix0 = (int)fx0;
    int base0 = (((b0 << 9) + iy0) << 9) + ix0;
    int a_tl0 = (base0 << 2) + cg0;
    int a_bl0 = a_tl0 + (Ww << 2);

    // ---- element 1 address math ----
    int x1 = p1 & (Ww - 1);
    int y1 = (p1 >> 9) & (Hh - 1);
    int b1 = p1 >> 18;
    float qy1 = (float)y1 - f1.x;
    float qx1 = (float)x1 - f1.y;
    float fy1 = fminf(fmaxf(floorf(qy1), 0.0f), (float)(Hh - 2));
    float fx1 = fminf(fmaxf(floorf(qx1), 0.0f), (float)(Ww - 2));
    float ay1 = fminf(fmaxf(qy1 - fy1, 0.0f), 1.0f);
    float ax1 = fminf(fmaxf(qx1 - fx1, 0.0f), 1.0f);
    int iy1 = (int)fy1, ix1 = (int)fx1;
    int base1 = (((b1 << 9) + iy1) << 9) + ix1;
    int a_tl1 = (base1 << 2) + cg1;
    int a_bl1 = a_tl1 + (Ww << 2);

    // ---- issue all 8 gathers back-to-back (independent) ----
    float4 tl0 = __ldg(&img4[a_tl0]);
    float4 tr0 = __ldg(&img4[a_tl0 + 4]);
    float4 bl0 = __ldg(&img4[a_bl0]);
    float4 br0 = __ldg(&img4[a_bl0 + 4]);
    float4 tl1 = __ldg(&img4[a_tl1]);
    float4 tr1 = __ldg(&img4[a_tl1 + 4]);
    float4 bl1 = __ldg(&img4[a_bl1]);
    float4 br1 = __ldg(&img4[a_bl1 + 4]);

    // ---- element 0 interp + store ----
    {
        float4 top, bot, r;
        top.x = fmaf(ax0, tr0.x - tl0.x, tl0.x);
        top.y = fmaf(ax0, tr0.y - tl0.y, tl0.y);
        top.z = fmaf(ax0, tr0.z - tl0.z, tl0.z);
        top.w = fmaf(ax0, tr0.w - tl0.w, tl0.w);
        bot.x = fmaf(ax0, br0.x - bl0.x, bl0.x);
        bot.y = fmaf(ax0, br0.y - bl0.y, bl0.y);
        bot.z = fmaf(ax0, br0.z - bl0.z, bl0.z);
        bot.w = fmaf(ax0, br0.w - bl0.w, bl0.w);
        r.x = fmaf(ay0, bot.x - top.x, top.x);
        r.y = fmaf(ay0, bot.y - top.y, top.y);
        r.z = fmaf(ay0, bot.z - top.z, top.z);
        r.w = fmaf(ay0, bot.w - top.w, top.w);
        out4[t0] = r;
    }
    // ---- element 1 interp + store ----
    {
        float4 top, bot, r;
        top.x = fmaf(ax1, tr1.x - tl1.x, tl1.x);
        top.y = fmaf(ax1, tr1.y - tl1.y, tl1.y);
        top.z = fmaf(ax1, tr1.z - tl1.z, tl1.z);
        top.w = fmaf(ax1, tr1.w - tl1.w, tl1.w);
        bot.x = fmaf(ax1, br1.x - bl1.x, bl1.x);
        bot.y = fmaf(ax1, br1.y - bl1.y, bl1.y);
        bot.z = fmaf(ax1, br1.z - bl1.z, bl1.z);
        bot.w = fmaf(ax1, br1.w - bl1.w, bl1.w);
        r.x = fmaf(ay1, bot.x - top.x, top.x);
        r.y = fmaf(ay1, bot.y - top.y, top.y);
        r.z = fmaf(ay1, bot.z - top.z, top.z);
        r.w = fmaf(ay1, bot.w - top.w, top.w);
        out4[t1] = r;
    }
}

extern "C" void kernel_launch(void* const* d_in, const int* in_sizes, int n_in,
                              void* d_out, int out_size)
{
    const float4* img4  = (const float4*)d_in[0];
    const float2* flow2 = (const float2*)d_in[1];
    float4* out4 = (float4*)d_out;

    int n4 = out_size / 4;     // 8,388,608 float4 elements
    int half = n4 / 2;         // 4,194,304 threads
    int block = 256;
    int grid = (half + block - 1) / block;
    warp_kernel2<<<grid, block>>>(img4, flow2, out4, half);
}

// round 4
// speedup vs baseline: 1.0685x; 1.0685x over previous
#include <cuda_runtime.h>

// dense_image_warp: out[b,y,x,c] = bilinear(image[b], y - flow[b,y,x,0], x - flow[b,y,x,1])
// B=8, H=512, W=512, C=16, fp32.
// 2-D tiling: each 256-thread block covers a 16(w) x 4(h) pixel tile x 4 channel
// groups, so the gather footprint (~18x6 px window) stays resident in L1 and
// vertical neighbor reuse happens inside the block instead of across blocks.

#define Hh 512
#define Ww 512
#define TW 16   // tile width (pixels)
#define TH 4    // tile height (pixels)

__global__ __launch_bounds__(256) void warp_kernel_tile(
    const float4* __restrict__ img4,   // image as float4 (4 channels per group)
    const float2* __restrict__ flow2,  // flow as float2 per pixel
    float4* __restrict__ out4)
{
    int t  = threadIdx.x;
    int cg = t & 3;           // channel group
    int lx = (t >> 2) & (TW - 1);
    int ly = t >> 6;          // 0..3

    int x = blockIdx.x * TW + lx;
    int y = blockIdx.y * TH + ly;
    int b = blockIdx.z;

    int p = (((b << 9) + y) << 9) + x;   // pixel index

    float2 f = __ldg(&flow2[p]);
    float qy = (float)y - f.x;
    float qx = (float)x - f.y;

    float fy = fminf(fmaxf(floorf(qy), 0.0f), (float)(Hh - 2));
    float fx = fminf(fmaxf(floorf(qx), 0.0f), (float)(Ww - 2));
    float ay = fminf(fmaxf(qy - fy, 0.0f), 1.0f);
    float ax = fminf(fmaxf(qx - fx, 0.0f), 1.0f);
    int iy = (int)fy;
    int ix = (int)fx;

    int base = (((b << 9) + iy) << 9) + ix;   // TL pixel index
    int a_tl = (base << 2) + cg;
    int a_bl = a_tl + (Ww << 2);

    float4 tl = __ldg(&img4[a_tl]);
    float4 tr = __ldg(&img4[a_tl + 4]);
    float4 bl = __ldg(&img4[a_bl]);
    float4 br = __ldg(&img4[a_bl + 4]);

    float4 top, bot, r;
    top.x = fmaf(ax, tr.x - tl.x, tl.x);
    top.y = fmaf(ax, tr.y - tl.y, tl.y);
    top.z = fmaf(ax, tr.z - tl.z, tl.z);
    top.w = fmaf(ax, tr.w - tl.w, tl.w);
    bot.x = fmaf(ax, br.x - bl.x, bl.x);
    bot.y = fmaf(ax, br.y - bl.y, bl.y);
    bot.z = fmaf(ax, br.z - bl.z, bl.z);
    bot.w = fmaf(ax, br.w - bl.w, bl.w);
    r.x = fmaf(ay, bot.x - top.x, top.x);
    r.y = fmaf(ay, bot.y - top.y, top.y);
    r.z = fmaf(ay, bot.z - top.z, top.z);
    r.w = fmaf(ay, bot.w - top.w, top.w);

    out4[(p << 2) + cg] = r;
}

extern "C" void kernel_launch(void* const* d_in, const int* in_sizes, int n_in,
                              void* d_out, int out_size)
{
    const float4* img4  = (const float4*)d_in[0];
    const float2* flow2 = (const float2*)d_in[1];
    float4* out4 = (float4*)d_out;

    dim3 grid(Ww / TW, Hh / TH, 8);
    warp_kernel_tile<<<grid, 256>>>(img4, flow2, out4);
}

// round 5
// speedup vs baseline: 1.0951x; 1.0249x over previous
#include <cuda_runtime.h>
#include <cstdint>

// dense_image_warp: out[b,y,x,c] = bilinear(image[b], y - flow[b,y,x,0], x - flow[b,y,x,1])
// B=8, H=512, W=512, C=16, fp32.
// Block = 256 threads = 16(w) x 4(h) pixels x 4 channel groups.
// Each block iterates 4 sub-tiles to cover a 16x16 pixel region.
// Flow for the whole 16x16 region is staged into smem via cp.async up front,
// so the per-iteration flow DRAM stall disappears (LDS instead of LDG).

#define Hh 512
#define Ww 512

__global__ __launch_bounds__(256) void warp_kernel_pf(
    const float4* __restrict__ img4,   // image as float4 (4 channels per group)
    const float2* __restrict__ flow2,  // flow as float2 per pixel
    float4* __restrict__ out4)
{
    __shared__ float2 sflow[256];      // 16x16 pixel flow tile

    int t  = threadIdx.x;
    int cg = t & 3;                    // channel group
    int lx = (t >> 2) & 15;            // 0..15
    int ly = t >> 6;                   // 0..3

    int x  = blockIdx.x * 16 + lx;
    int y0 = blockIdx.y * 16;
    int b  = blockIdx.z;

    // ---- stage flow tile: thread t loads tile pixel (t&15, t>>4) ----
    {
        int fxp = blockIdx.x * 16 + (t & 15);
        int fyp = y0 + (t >> 4);
        int fp  = (((b << 9) + fyp) << 9) + fxp;
        uint32_t saddr = (uint32_t)__cvta_generic_to_shared(&sflow[t]);
        asm volatile("cp.async.ca.shared.global [%0], [%1], 8;\n"
                     :: "r"(saddr), "l"(&flow2[fp]) : "memory");
    }
    asm volatile("cp.async.commit_group;\n" ::: "memory");
    asm volatile("cp.async.wait_group 0;\n" ::: "memory");
    __syncthreads();

    #pragma unroll
    for (int it = 0; it < 4; it++) {
        int y = y0 + it * 4 + ly;

        float2 f = sflow[((it * 4 + ly) << 4) + lx];
        float qy = (float)y - f.x;
        float qx = (float)x - f.y;

        float fy = fminf(fmaxf(floorf(qy), 0.0f), (float)(Hh - 2));
        float fx = fminf(fmaxf(floorf(qx), 0.0f), (float)(Ww - 2));
        float ay = fminf(fmaxf(qy - fy, 0.0f), 1.0f);
        float ax = fminf(fmaxf(qx - fx, 0.0f), 1.0f);
        int iy = (int)fy;
        int ix = (int)fx;

        int base = (((b << 9) + iy) << 9) + ix;   // TL pixel index
        int a_tl = (base << 2) + cg;
        int a_bl = a_tl + (Ww << 2);

        float4 tl = __ldg(&img4[a_tl]);
        float4 tr = __ldg(&img4[a_tl + 4]);
        float4 bl = __ldg(&img4[a_bl]);
        float4 br = __ldg(&img4[a_bl + 4]);

        float4 top, bot, r;
        top.x = fmaf(ax, tr.x - tl.x, tl.x);
        top.y = fmaf(ax, tr.y - tl.y, tl.y);
        top.z = fmaf(ax, tr.z - tl.z, tl.z);
        top.w = fmaf(ax, tr.w - tl.w, tl.w);
        bot.x = fmaf(ax, br.x - bl.x, bl.x);
        bot.y = fmaf(ax, br.y - bl.y, bl.y);
        bot.z = fmaf(ax, br.z - bl.z, bl.z);
        bot.w = fmaf(ax, br.w - bl.w, bl.w);
        r.x = fmaf(ay, bot.x - top.x, top.x);
        r.y = fmaf(ay, bot.y - top.y, top.y);
        r.z = fmaf(ay, bot.z - top.z, top.z);
        r.w = fmaf(ay, bot.w - top.w, top.w);

        int p = (((b << 9) + y) << 9) + x;
        out4[(p << 2) + cg] = r;
    }
}

extern "C" void kernel_launch(void* const* d_in, const int* in_sizes, int n_in,
                              void* d_out, int out_size)
{
    const float4* img4  = (const float4*)d_in[0];
    const float2* flow2 = (const float2*)d_in[1];
    float4* out4 = (float4*)d_out;

    dim3 grid(Ww / 16, Hh / 16, 8);
    warp_kernel_pf<<<grid, 256>>>(img4, flow2, out4);
}